// round 8
// baseline (speedup 1.0000x reference)
#include <cuda_runtime.h>
#include <math.h>

#define BB      16
#define NA      286
#define NAP     288       // padded atom count (multiple of 16)
#define HID     150
#define HIDP    160
#define FF      512
#define RADIUS_F 3.0f
#define MT      512       // table knots per cloud
#define PTS     4         // points per build block
#define CH      10        // k-chunk (prefetch depth) in build

// ---------------- scratch (device globals; no allocation allowed) ----------
__device__ __align__(16) float g_feats0[BB*NA*4];
__device__ __align__(16) float g_f1[BB*NA*4];
__device__ __align__(16) float g_f2[BB*NA*4];
// paired-knot table: knot i holds {K_i[q][0..3], K_{i+1}[q][0..3]} per q -> 32 floats/knot
__device__ __align__(16) float g_tab2[2][MT*32];
__device__ float g_wpad[4][HID*HIDP];     // c0_w1, c0_w2, c1_w1, c1_w2 (160-wide rows)
__device__ float g_nbinv[BB*NA];
__device__ float g_h[BB*FF];

__device__ __forceinline__ float sp5(float x) {
    float z = 5.0f * x;
    return (fmaxf(z, 0.0f) + log1pf(expf(-fabsf(z)))) * 0.2f;
}
__device__ __forceinline__ float softplus1(float x) {
    return fmaxf(x, 0.0f) + log1pf(expf(-fabsf(x)));
}

// ---------------- 1. fused embedding gather + weight padding --------------
__global__ void k_embed_pad(const int* __restrict__ Z, const float* __restrict__ emb,
                            const float* __restrict__ a, const float* __restrict__ b,
                            const float* __restrict__ c, const float* __restrict__ d) {
    int m = blockIdx.y;
    int i = blockIdx.x * blockDim.x + threadIdx.x;
    if (m < 4) {
        const float* srcs[4] = {a, b, c, d};
        const float* src = srcs[m];
        if (i < HID*HIDP) {
            int k = i / HIDP;
            int o = i - k*HIDP;
            g_wpad[m][i] = (o < HID) ? src[k*HID + o] : 0.0f;
        }
    } else {
        if (i < BB*NA) {
            int zi = Z[i];
            float4 e = *(const float4*)(emb + zi*4);
            *(float4*)(g_feats0 + i*4) = e;
        }
    }
}

// ---------------- 2. radial-MLP table build (output-parallel, prefetched) --
struct CloudW {
    const float* w0; const float* b0;
    const float* b1; const float* b2;
    const float* w3; const float* b3;
};
struct BuildArgs { CloudW c[2]; };

__global__ void __launch_bounds__(HIDP) k_build(BuildArgs args) {
    int cloud = blockIdx.y;
    CloudW cw = args.c[cloud];
    int t = threadIdx.x;                 // 0..159
    int pt0 = blockIdx.x * PTS;

    __shared__ float4 X0[HIDP];
    __shared__ float4 X1[HIDP];
    __shared__ float red[10][PTS][16];

    bool ok = (t < HID);

    float bas[PTS][3];
    const float hstep = RADIUS_F / (float)(MT - 1);
    #pragma unroll
    for (int p = 0; p < PTS; p++) {
        float r = (float)(pt0 + p) * hstep;
        #pragma unroll
        for (int j = 0; j < 3; j++) {
            float dd = (r - 1.5f * (float)j) * (1.0f / 1.5f);
            float cv = cosf(1.57079632679489662f * dd);
            bas[p][j] = (fabsf(dd) < 1.0f) ? cv * cv : 0.0f;
        }
    }

    // layer 0: 3 -> 150
    {
        float w0a = ok ? cw.w0[t]         : 0.0f;
        float w0b = ok ? cw.w0[HID + t]   : 0.0f;
        float w0c = ok ? cw.w0[2*HID + t] : 0.0f;
        float bb0 = ok ? cw.b0[t]         : 0.0f;
        float4 v;
        float* vp = (float*)&v;
        #pragma unroll
        for (int p = 0; p < PTS; p++) {
            float av = bb0;
            av = fmaf(bas[p][0], w0a, av);
            av = fmaf(bas[p][1], w0b, av);
            av = fmaf(bas[p][2], w0c, av);
            vp[p] = sp5(av);
        }
        X0[t] = v;
    }
    __syncthreads();

    // layers 1 & 2: 150 -> 150, register-prefetched weight chunks
    #pragma unroll
    for (int L = 0; L < 2; ++L) {
        const float* wp = g_wpad[2*cloud + L];
        const float* bb = (L == 0) ? cw.b1 : cw.b2;
        const float4* S = (L == 0) ? X0 : X1;
        float4*       D = (L == 0) ? X1 : X0;

        float bv = ok ? bb[t] : 0.0f;
        float acc0 = bv, acc1 = bv, acc2 = bv, acc3 = bv;

        float wbuf[CH];
        #pragma unroll
        for (int j = 0; j < CH; j++) wbuf[j] = wp[j*HIDP + t];

        for (int k0 = 0; k0 < HID; k0 += CH) {   // 15 chunks
            float wn[CH];
            bool more = (k0 + CH < HID);
            #pragma unroll
            for (int j = 0; j < CH; j++)
                wn[j] = more ? wp[(k0 + CH + j)*HIDP + t] : 0.0f;
            #pragma unroll
            for (int j = 0; j < CH; j++) {
                float4 x = S[k0 + j];
                acc0 = fmaf(x.x, wbuf[j], acc0);
                acc1 = fmaf(x.y, wbuf[j], acc1);
                acc2 = fmaf(x.z, wbuf[j], acc2);
                acc3 = fmaf(x.w, wbuf[j], acc3);
            }
            #pragma unroll
            for (int j = 0; j < CH; j++) wbuf[j] = wn[j];
        }
        float4 dv;
        dv.x = sp5(acc0); dv.y = sp5(acc1); dv.z = sp5(acc2); dv.w = sp5(acc3);
        D[t] = dv;
        __syncthreads();
    }

    // layer 3: 150 -> 16, split k across 10 chunks of 15 (source is X0)
    {
        int o = t & 15, c = t >> 4;
        float a0 = 0.f, a1 = 0.f, a2 = 0.f, a3 = 0.f;
        #pragma unroll
        for (int kk = 0; kk < 15; kk++) {
            int k = c*15 + kk;
            float w = cw.w3[k*16 + o];
            float4 x = X0[k];
            a0 = fmaf(x.x, w, a0);
            a1 = fmaf(x.y, w, a1);
            a2 = fmaf(x.z, w, a2);
            a3 = fmaf(x.w, w, a3);
        }
        red[c][0][o] = a0; red[c][1][o] = a1;
        red[c][2][o] = a2; red[c][3][o] = a3;
    }
    __syncthreads();
    if (t < 16*PTS) {
        int o = t & 15, p = t >> 4;
        float s = cw.b3[o];
        #pragma unroll
        for (int c = 0; c < 10; c++) s += red[c][p][o];
        int pt = pt0 + p;
        int q = o >> 2, j = o & 3;
        // this knot's k0 slot
        g_tab2[cloud][pt*32 + q*8 + j] = s;
        // previous knot's k1 slot
        if (pt > 0)
            g_tab2[cloud][(pt-1)*32 + q*8 + 4 + j] = s;
    }
}

// ---------------- 3. pair convolution (inline dist + table interp) --------
// grid (NAP/4, BB), 256 threads, 2 warps per atom (16 pair slots).
// Lane = 4 channels (q) x 8 slots; warp parity h gives slots 0-7 / 8-15.
template<int CLOUD>
__global__ void __launch_bounds__(256) k_conv(const float* __restrict__ xyz) {
    int z = blockIdx.y;
    const float* feats = CLOUD ? g_f1 : g_feats0;
    float*       out   = CLOUD ? g_f2 : g_f1;
    const float* tab   = g_tab2[CLOUD];

    __shared__ float4 sc[NAP];
    __shared__ float4 sf[NAP];
    __shared__ float red[4][2][4];
    __shared__ int   redc[4][2];

    const float*  xr = xyz + (size_t)z * NA * 3;
    const float4* fz = (const float4*)(feats + (size_t)z * NA * 4);
    for (int i = threadIdx.x; i < NAP; i += 256) {
        if (i < NA) {
            sc[i] = make_float4(xr[i*3+0], xr[i*3+1], xr[i*3+2], 0.f);
            sf[i] = fz[i];
        } else {
            sc[i] = make_float4(1.0e6f, 1.0e6f, 1.0e6f, 0.f);
            sf[i] = make_float4(0.f, 0.f, 0.f, 0.f);
        }
    }
    __syncthreads();

    int warp = threadIdx.x >> 5, lane = threadIdx.x & 31;
    int aa = warp >> 1, h = warp & 1;
    int q = lane & 3;
    int p = (lane >> 2) + h*8;       // slot 0..15
    int a = blockIdx.x * 4 + aa;
    float4 ac = sc[a];
    const float uscale = (float)(MT - 1) / RADIUS_F;

    float acc = 0.0f;
    int cnt = 0;
    #pragma unroll 6
    for (int it = 0; it < NAP/16; it++) {
        int b = p + it*16;
        float4 bc = sc[b];
        float dx = ac.x - bc.x;
        float dy = ac.y - bc.y;
        float dz = ac.z - bc.z;
        float d2 = fmaf(dx, dx, fmaf(dy, dy, dz*dz));
        if (d2 < 9.0f) {
            cnt++;
            float u = fminf(sqrtf(d2) * uscale, 510.999f);
            int i0 = (int)u;
            float tt = u - (float)i0;
            const float* bp = tab + i0*32 + q*8;
            float4 k0 = *(const float4*)bp;
            float4 k1 = *(const float4*)(bp + 4);
            float4 f = sf[b];
            acc += fmaf(tt, k1.x - k0.x, k0.x) * f.x
                 + fmaf(tt, k1.y - k0.y, k0.y) * f.y
                 + fmaf(tt, k1.z - k0.z, k0.z) * f.z
                 + fmaf(tt, k1.w - k0.w, k0.w) * f.w;
        }
    }
    // reduce over the 8 slots within this warp (lanes differing in bits 2..4)
    acc += __shfl_down_sync(0xffffffffu, acc, 16);
    acc += __shfl_down_sync(0xffffffffu, acc, 8);
    acc += __shfl_down_sync(0xffffffffu, acc, 4);
    if (CLOUD == 0) {
        cnt += __shfl_down_sync(0xffffffffu, cnt, 16);
        cnt += __shfl_down_sync(0xffffffffu, cnt, 8);
        cnt += __shfl_down_sync(0xffffffffu, cnt, 4);
        if (lane == 0) redc[aa][h] = cnt;
    }
    if (lane < 4) red[aa][h][q] = acc;
    __syncthreads();

    if (threadIdx.x < 16) {
        int aa2 = threadIdx.x >> 2, q2 = threadIdx.x & 3;
        int a2 = blockIdx.x * 4 + aa2;
        if (a2 < NA) {
            float s = red[aa2][0][q2] + red[aa2][1][q2];
            float nb;
            if (CLOUD == 0) {
                int c = redc[aa2][0] + redc[aa2][1];
                nb = rsqrtf((float)max(c, 1));
                if (q2 == 0) g_nbinv[z*NA + a2] = nb;
            } else {
                nb = g_nbinv[z*NA + a2];
            }
            out[((size_t)z*NA + a2)*4 + q2] = s * nb;
        }
    }
}

// ---------------- 4. fused L2-pool + FC + softplus ------------------------
__global__ void __launch_bounds__(FF) k_poolfc(const float* __restrict__ fcw,
                                               const float* __restrict__ fcb) {
    int z = blockIdx.x;
    int lane = threadIdx.x & 31, warp = threadIdx.x >> 5;
    __shared__ float sm[16][8];
    __shared__ float spool[8];

    float s[8] = {0,0,0,0,0,0,0,0};
    for (int a = threadIdx.x; a < NA; a += FF) {
        float4 f1 = *(const float4*)(g_f1 + ((size_t)z*NA + a)*4);
        float4 f2 = *(const float4*)(g_f2 + ((size_t)z*NA + a)*4);
        s[0] += f1.x*f1.x; s[1] += f1.y*f1.y; s[2] += f1.z*f1.z; s[3] += f1.w*f1.w;
        s[4] += f2.x*f2.x; s[5] += f2.y*f2.y; s[6] += f2.z*f2.z; s[7] += f2.w*f2.w;
    }
    #pragma unroll
    for (int j = 0; j < 8; j++)
        for (int off = 16; off; off >>= 1) s[j] += __shfl_down_sync(0xffffffffu, s[j], off);
    if (lane == 0) {
        #pragma unroll
        for (int j = 0; j < 8; j++) sm[warp][j] = s[j];
    }
    __syncthreads();
    if (threadIdx.x < 8) {
        float t = 0.0f;
        #pragma unroll
        for (int w = 0; w < 16; w++) t += sm[w][threadIdx.x];
        spool[threadIdx.x] = sqrtf(t);
    }
    __syncthreads();
    int f = threadIdx.x;
    float a = fcb[f];
    #pragma unroll
    for (int c = 0; c < 8; c++) a = fmaf(spool[c], fcw[c*FF + f], a);
    g_h[z*FF + f] = softplus1(a);
}

// ---------------- 5. fused batch-stats + batchnorm + output head ----------
__global__ void __launch_bounds__(FF) k_statsout(const float* __restrict__ bng,
                                                 const float* __restrict__ bnb,
                                                 const float* __restrict__ ow,
                                                 const float* __restrict__ ob,
                                                 float* __restrict__ out) {
    int f = threadIdx.x;
    int lane = f & 31, warp = f >> 5;
    __shared__ float smw[16][BB];

    float hv[BB];
    float m = 0.0f;
    #pragma unroll
    for (int z = 0; z < BB; z++) { hv[z] = g_h[z*FF + f]; m += hv[z]; }
    m *= (1.0f / (float)BB);
    float v = 0.0f;
    #pragma unroll
    for (int z = 0; z < BB; z++) { float d = hv[z] - m; v += d*d; }
    v *= (1.0f / (float)BB);
    float sc = rsqrtf(v + 1e-5f) * bng[f];
    float bo = bnb[f];
    float w  = ow[f];

    float acc[BB];
    #pragma unroll
    for (int z = 0; z < BB; z++)
        acc[z] = softplus1((hv[z] - m) * sc + bo) * w;

    #pragma unroll
    for (int z = 0; z < BB; z++)
        for (int off = 16; off; off >>= 1)
            acc[z] += __shfl_down_sync(0xffffffffu, acc[z], off);
    if (lane == 0) {
        #pragma unroll
        for (int z = 0; z < BB; z++) smw[warp][z] = acc[z];
    }
    __syncthreads();
    if (f < BB) {
        float t = ob[0];
        #pragma unroll
        for (int wI = 0; wI < 16; wI++) t += smw[wI][f];
        out[f] = 1.0f / (1.0f + expf(-t));
    }
}

// ---------------- launch --------------------------------------------------
extern "C" void kernel_launch(void* const* d_in, const int* in_sizes, int n_in,
                              void* d_out, int out_size) {
    const float* xyz   = (const float*)d_in[0];
    const int*   Z     = (const int*)  d_in[1];
    const float* emb   = (const float*)d_in[2];
    const float* c0_w0 = (const float*)d_in[3];
    const float* c0_b0 = (const float*)d_in[4];
    const float* c0_w1 = (const float*)d_in[5];
    const float* c0_b1 = (const float*)d_in[6];
    const float* c0_w2 = (const float*)d_in[7];
    const float* c0_b2 = (const float*)d_in[8];
    const float* c0_w3 = (const float*)d_in[9];
    const float* c0_b3 = (const float*)d_in[10];
    const float* c1_w0 = (const float*)d_in[11];
    const float* c1_b0 = (const float*)d_in[12];
    const float* c1_w1 = (const float*)d_in[13];
    const float* c1_b1 = (const float*)d_in[14];
    const float* c1_w2 = (const float*)d_in[15];
    const float* c1_b2 = (const float*)d_in[16];
    const float* c1_w3 = (const float*)d_in[17];
    const float* c1_b3 = (const float*)d_in[18];
    const float* fc_w  = (const float*)d_in[19];
    const float* fc_b  = (const float*)d_in[20];
    const float* bn_g  = (const float*)d_in[21];
    const float* bn_b  = (const float*)d_in[22];
    const float* out_w = (const float*)d_in[23];
    const float* out_b = (const float*)d_in[24];
    float* out = (float*)d_out;

    k_embed_pad<<<dim3((HID*HIDP + 255) / 256, 5), 256>>>(Z, emb, c0_w1, c0_w2, c1_w1, c1_w2);

    BuildArgs ba;
    ba.c[0].w0 = c0_w0; ba.c[0].b0 = c0_b0; ba.c[0].b1 = c0_b1; ba.c[0].b2 = c0_b2;
    ba.c[0].w3 = c0_w3; ba.c[0].b3 = c0_b3;
    ba.c[1].w0 = c1_w0; ba.c[1].b0 = c1_b0; ba.c[1].b1 = c1_b1; ba.c[1].b2 = c1_b2;
    ba.c[1].w3 = c1_w3; ba.c[1].b3 = c1_b3;
    k_build<<<dim3(MT / PTS, 2), HIDP>>>(ba);

    dim3 cg(NAP / 4, BB);
    k_conv<0><<<cg, 256>>>(xyz);
    k_conv<1><<<cg, 256>>>(xyz);
    k_poolfc<<<BB, FF>>>(fc_w, fc_b);
    k_statsout<<<1, FF>>>(bn_g, bn_b, out_w, out_b, out);
}